// round 13
// baseline (speedup 1.0000x reference)
#include <cuda_runtime.h>
#include <cuda_fp16.h>
#include <cstdint>

#define WSIZE 9216
#define PSTRIDE 9248

#define XPITCH 20                        // words/pixel: 16 data + 4 pad (conflict-free, proven R5)
#define XROWW  (130 * XPITCH)            // 2600
#define XT_WORDS (6 * XROWW)             // 15600
#define WPITCH 148                       // words/filter: 144 data + 4 pad (proven R5)
#define WT_WORDS (32 * WPITCH)           // 4736
#define SMEM_BYTES ((XT_WORDS + WT_WORDS) * 4)   // 81344 -> 2 CTAs/SM

// precomputed W^T fp16, k-major, FILTER-PERMUTED:
// stored position p holds logical filter f = 8*((p&7)>>1) + 2*(p>>3) + (p&1)
// => mma lane (g,t) owns logical channels 8t..8t+7 contiguously (coalesced epilogue)
__device__ uint32_t gWT[32 * WT_WORDS];

__device__ __forceinline__ uint32_t pack2(float a, float b) {
    __half2 h = __floats2half2_rn(a, b);
    return *(uint32_t*)&h;
}
__device__ __forceinline__ void mma_f16(float& c0, float& c1, float& c2, float& c3,
                                        uint32_t a0, uint32_t a1, uint32_t a2, uint32_t a3,
                                        uint32_t b0, uint32_t b1) {
    asm volatile(
        "mma.sync.aligned.m16n8k16.row.col.f32.f16.f16.f32 "
        "{%0,%1,%2,%3}, {%4,%5,%6,%7}, {%8,%9}, {%0,%1,%2,%3};"
        : "+f"(c0), "+f"(c1), "+f"(c2), "+f"(c3)
        : "r"(a0), "r"(a1), "r"(a2), "r"(a3), "r"(b0), "r"(b1));
}

// ---- precompute W^T fp16 (k-major, permuted filters), 9 small blocks/batch ----
__global__ __launch_bounds__(256)
void wprep(const float* __restrict__ params) {
    __shared__ float s[32 * 33];
    const int b  = blockIdx.x / 9;
    const int kc = blockIdx.x % 9;       // k chunk [kc*32, kc*32+32)
    const int tid = threadIdx.x;
    const float* pw = params + (long)b * PSTRIDE + kc * 1024;
    #pragma unroll
    for (int i = tid; i < 1024; i += 256) {
        int k = i >> 5, f = i & 31;
        s[k * 33 + f] = pw[i];
    }
    __syncthreads();
    uint32_t* gw = gWT + b * WT_WORDS + kc * 16;
    #pragma unroll
    for (int i = tid; i < 512; i += 256) {
        int p = i >> 4, n = i & 15;      // p = stored filter position
        int fl = 8 * ((p & 7) >> 1) + 2 * (p >> 3) + (p & 1);   // logical filter
        gw[p * WPITCH + n] = pack2(s[(2 * n) * 33 + fl], s[(2 * n + 1) * 33 + fl]);
    }
}

__global__ __launch_bounds__(256, 2)
void conv_mma_f16(const float* __restrict__ x, const float* __restrict__ params,
                  float* __restrict__ out) {
    extern __shared__ uint32_t smem[];
    uint32_t* sX = smem;                 // [row 0..5][pix 0..129][XPITCH], fp16 k-major
    uint32_t* sW = smem + XT_WORDS;      // [stored f][WPITCH], fp16 k-major

    const int tid = threadIdx.x;
    const int wid = tid >> 5;
    const int lid = tid & 31;
    const int g   = lid >> 2;
    const int t   = lid & 3;
    const int y0  = blockIdx.x * 4;      // 4 output rows per CTA
    const int b   = blockIdx.y;

    // ---- copy precomputed W^T (uint4 memcpy) ----
    const uint4* gw4 = (const uint4*)(gWT + b * WT_WORDS);
    #pragma unroll
    for (int it = 0; it < 5; it++) {
        int idx = tid + it * 256;
        if (idx < WT_WORDS / 4) ((uint4*)sW)[idx] = gw4[idx];
    }

    // ---- build X tile: input rows y0-1 .. y0+4, pixels -1..128 at 0..129 ----
    const float* xb = x + (long)b * (128 * 128 * 32);
    #pragma unroll
    for (int it = 0; it < 24; it++) {
        int idx = tid + it * 256;        // 0..6143
        int c4  = idx & 7;
        int px  = (idx >> 3) & 127;
        int row = idx >> 10;             // 0..5
        int gy  = y0 + row - 1;
        uint2 v = make_uint2(0u, 0u);
        if ((unsigned)gy < 128u) {
            float4 s = *(const float4*)(xb + ((gy * 128 + px) * 32 + c4 * 4));
            v.x = pack2(s.x, s.y);
            v.y = pack2(s.z, s.w);
        }
        *(uint2*)(sX + row * XROWW + (px + 1) * XPITCH + c4 * 2) = v;
    }
    if (tid < 192) {
        int row = tid >> 5, rem = tid & 31;
        int pix = (rem >> 4) ? 129 : 0;
        sX[row * XROWW + pix * XPITCH + (rem & 15)] = 0u;
    }
    __syncthreads();

    const int yl = wid >> 1;             // local output row 0..3
    const int m0 = (wid & 1) * 64;       // 64 px per warp

    float acc[4][4][4];
    #pragma unroll
    for (int mi = 0; mi < 4; mi++)
        #pragma unroll
        for (int nt = 0; nt < 4; nt++)
            #pragma unroll
            for (int j = 0; j < 4; j++) acc[mi][nt][j] = 0.f;

    #pragma unroll
    for (int kh = 0; kh < 3; kh++) {
        const uint32_t* xr = sX + (yl + kh) * XROWW;
        #pragma unroll
        for (int kw = 0; kw < 3; kw++) {
            #pragma unroll
            for (int c16 = 0; c16 < 2; c16++) {
                const int k0w = kh * 48 + kw * 16 + c16 * 8;

                // B fragments (scalar LDS, proven conflict-free)
                uint32_t b0[4], b1[4];
                const uint32_t* wp = sW + k0w + t;
                #pragma unroll
                for (int nt = 0; nt < 4; nt++) {
                    int f = nt * 8 + g;
                    b0[nt] = wp[f * WPITCH];
                    b1[nt] = wp[f * WPITCH + 4];
                }

                #pragma unroll
                for (int mi = 0; mi < 4; mi++) {
                    const uint32_t* ap = xr + (m0 + mi * 16 + g + kw) * XPITCH
                                            + c16 * 8 + t;
                    uint32_t a0 = ap[0];
                    uint32_t a1 = ap[8 * XPITCH];
                    uint32_t a2 = ap[4];
                    uint32_t a3 = ap[8 * XPITCH + 4];
                    #pragma unroll
                    for (int nt = 0; nt < 4; nt++)
                        mma_f16(acc[mi][nt][0], acc[mi][nt][1],
                                acc[mi][nt][2], acc[mi][nt][3],
                                a0, a1, a2, a3, b0[nt], b1[nt]);
                }
            }
        }
    }

    // ---- epilogue: + bias, coalesced STG.128 (lane owns logical ch 8t..8t+7) ----
    const float* bp = params + (long)b * PSTRIDE + WSIZE;
    float bb[8];
    {
        float4 b04 = *(const float4*)(bp + 8 * t);
        float4 b48 = *(const float4*)(bp + 8 * t + 4);
        bb[0] = b04.x; bb[1] = b04.y; bb[2] = b04.z; bb[3] = b04.w;
        bb[4] = b48.x; bb[5] = b48.y; bb[6] = b48.z; bb[7] = b48.w;
    }
    float* ob = out + ((long)(b * 128 + y0 + yl)) * 128 * 32;
    #pragma unroll
    for (int mi = 0; mi < 4; mi++) {
        float o0[8], o1[8];
        #pragma unroll
        for (int nt = 0; nt < 4; nt++) {
            o0[2 * nt]     = acc[mi][nt][0] + bb[2 * nt];
            o0[2 * nt + 1] = acc[mi][nt][1] + bb[2 * nt + 1];
            o1[2 * nt]     = acc[mi][nt][2] + bb[2 * nt];
            o1[2 * nt + 1] = acc[mi][nt][3] + bb[2 * nt + 1];
        }
        const int px = m0 + mi * 16 + g;
        float* p0 = ob + px * 32 + 8 * t;
        float* p1 = ob + (px + 8) * 32 + 8 * t;
        *(float4*)(p0)     = make_float4(o0[0], o0[1], o0[2], o0[3]);
        *(float4*)(p0 + 4) = make_float4(o0[4], o0[5], o0[6], o0[7]);
        *(float4*)(p1)     = make_float4(o1[0], o1[1], o1[2], o1[3]);
        *(float4*)(p1 + 4) = make_float4(o1[4], o1[5], o1[6], o1[7]);
    }
}

extern "C" void kernel_launch(void* const* d_in, const int* in_sizes, int n_in,
                              void* d_out, int out_size) {
    const float* x      = (const float*)d_in[0];
    const float* params = (const float*)d_in[1];
    float* out          = (float*)d_out;

    wprep<<<288, 256>>>(params);

    cudaFuncSetAttribute(conv_mma_f16, cudaFuncAttributeMaxDynamicSharedMemorySize, SMEM_BYTES);
    dim3 grid(32, 32);   // (row-quad, batch)
    conv_mma_f16<<<grid, 256, SMEM_BYTES>>>(x, params, out);
}

// round 14
// speedup vs baseline: 1.0152x; 1.0152x over previous
#include <cuda_runtime.h>
#include <cuda_fp16.h>
#include <cstdint>

#define WSIZE 9216
#define PSTRIDE 9248

#define XPITCH 20                        // words/pixel: 16 data + 4 pad (conflict-free, proven R5)
#define XROWW  (130 * XPITCH)            // 2600
#define XT_WORDS (6 * XROWW)             // 15600
#define WPITCH 148                       // words/filter: 144 data + 4 pad (proven R5)
#define WT_WORDS (32 * WPITCH)           // 4736
#define ST_WORDS (144 * 33)              // 4752, fp16-pair staging [k2][f], pitch 33
#define SMEM_BYTES ((XT_WORDS + WT_WORDS + ST_WORDS) * 4)   // 100352 -> 2 CTAs/SM

__device__ __forceinline__ uint32_t pack2(float a, float b) {
    __half2 h = __floats2half2_rn(a, b);
    return *(uint32_t*)&h;
}
__device__ __forceinline__ void mma_f16(float& c0, float& c1, float& c2, float& c3,
                                        uint32_t a0, uint32_t a1, uint32_t a2, uint32_t a3,
                                        uint32_t b0, uint32_t b1) {
    asm volatile(
        "mma.sync.aligned.m16n8k16.row.col.f32.f16.f16.f32 "
        "{%0,%1,%2,%3}, {%4,%5,%6,%7}, {%8,%9}, {%0,%1,%2,%3};"
        : "+f"(c0), "+f"(c1), "+f"(c2), "+f"(c3)
        : "r"(a0), "r"(a1), "r"(a2), "r"(a3), "r"(b0), "r"(b1));
}

__global__ __launch_bounds__(256, 2)
void conv_mma_f16(const float* __restrict__ x, const float* __restrict__ params,
                  float* __restrict__ out) {
    extern __shared__ uint32_t smem[];
    uint32_t* sX = smem;                       // [row 0..5][pix 0..129][XPITCH], fp16 k-major
    uint32_t* sW = smem + XT_WORDS;            // [f][WPITCH], fp16 k-major
    uint32_t* sT = smem + XT_WORDS + WT_WORDS; // staging: [k2 0..143][f], pitch 33

    const int tid = threadIdx.x;
    const int wid = tid >> 5;
    const int lid = tid & 31;
    const int g   = lid >> 2;
    const int t   = lid & 3;
    const int y0  = blockIdx.x * 4;      // 4 output rows per CTA
    const int b   = blockIdx.y;

    const float* pw = params + (long)b * PSTRIDE;

    // ---- phase 1a: stage W as fp16 k-pairs, [k2][f] pitch 33 ----
    #pragma unroll
    for (int it = 0; it < 18; it++) {
        int i  = tid + it * 256;         // 0..4607
        int k2 = i >> 5;                 // 0..143
        int f  = i & 31;
        sT[k2 * 33 + f] = pack2(pw[k2 * 64 + f], pw[k2 * 64 + 32 + f]);  // coalesced LDG, cf STS
    }

    // ---- phase 1b: build X tile (independent smem region, same pass) ----
    const float* xb = x + (long)b * (128 * 128 * 32);
    #pragma unroll
    for (int it = 0; it < 24; it++) {
        int idx = tid + it * 256;        // 0..6143
        int c4  = idx & 7;
        int px  = (idx >> 3) & 127;
        int row = idx >> 10;             // 0..5
        int gy  = y0 + row - 1;
        uint2 v = make_uint2(0u, 0u);
        if ((unsigned)gy < 128u) {
            float4 s = *(const float4*)(xb + ((gy * 128 + px) * 32 + c4 * 4));
            v.x = pack2(s.x, s.y);
            v.y = pack2(s.z, s.w);
        }
        *(uint2*)(sX + row * XROWW + (px + 1) * XPITCH + c4 * 2) = v;
    }
    if (tid < 192) {
        int row = tid >> 5, rem = tid & 31;
        int pix = (rem >> 4) ? 129 : 0;
        sX[row * XROWW + pix * XPITCH + (rem & 15)] = 0u;
    }
    __syncthreads();

    // ---- phase 2: transpose staging -> sW[f][n] (conflict-free both sides) ----
    #pragma unroll
    for (int it = 0; it < 18; it++) {
        int i = tid + it * 256;          // 0..4607
        int f = i / 144, n = i - f * 144;
        sW[f * WPITCH + n] = sT[n * 33 + f];
    }
    __syncthreads();

    const int yl = wid >> 1;             // local output row 0..3
    const int m0 = (wid & 1) * 64;       // 64 px per warp

    float acc[4][4][4];
    #pragma unroll
    for (int mi = 0; mi < 4; mi++)
        #pragma unroll
        for (int nt = 0; nt < 4; nt++)
            #pragma unroll
            for (int j = 0; j < 4; j++) acc[mi][nt][j] = 0.f;

    #pragma unroll
    for (int kh = 0; kh < 3; kh++) {
        const uint32_t* xr = sX + (yl + kh) * XROWW;
        #pragma unroll
        for (int kw = 0; kw < 3; kw++) {
            #pragma unroll
            for (int c16 = 0; c16 < 2; c16++) {
                const int k0w = kh * 48 + kw * 16 + c16 * 8;

                // B fragments (scalar LDS, proven conflict-free)
                uint32_t b0[4], b1[4];
                const uint32_t* wp = sW + k0w + t;
                #pragma unroll
                for (int nt = 0; nt < 4; nt++) {
                    int f = nt * 8 + g;
                    b0[nt] = wp[f * WPITCH];
                    b1[nt] = wp[f * WPITCH + 4];
                }

                #pragma unroll
                for (int mi = 0; mi < 4; mi++) {
                    const uint32_t* ap = xr + (m0 + mi * 16 + g + kw) * XPITCH
                                            + c16 * 8 + t;
                    uint32_t a0 = ap[0];
                    uint32_t a1 = ap[8 * XPITCH];
                    uint32_t a2 = ap[4];
                    uint32_t a3 = ap[8 * XPITCH + 4];
                    #pragma unroll
                    for (int nt = 0; nt < 4; nt++)
                        mma_f16(acc[mi][nt][0], acc[mi][nt][1],
                                acc[mi][nt][2], acc[mi][nt][3],
                                a0, a1, a2, a3, b0[nt], b1[nt]);
                }
            }
        }
    }

    // ---- epilogue: + bias, direct STG (R5-proven) ----
    const float* bp = pw + WSIZE;
    float* ob = out + ((long)(b * 128 + y0 + yl)) * 128 * 32;
    #pragma unroll
    for (int nt = 0; nt < 4; nt++) {
        int f = nt * 8 + t * 2;
        float2 bias = *(const float2*)(bp + f);
        #pragma unroll
        for (int mi = 0; mi < 4; mi++) {
            int px = m0 + mi * 16 + g;
            float2 o0, o1;
            o0.x = acc[mi][nt][0] + bias.x;
            o0.y = acc[mi][nt][1] + bias.y;
            o1.x = acc[mi][nt][2] + bias.x;
            o1.y = acc[mi][nt][3] + bias.y;
            *(float2*)(ob + px * 32 + f)       = o0;
            *(float2*)(ob + (px + 8) * 32 + f) = o1;
        }
    }
}

extern "C" void kernel_launch(void* const* d_in, const int* in_sizes, int n_in,
                              void* d_out, int out_size) {
    const float* x      = (const float*)d_in[0];
    const float* params = (const float*)d_in[1];
    float* out          = (float*)d_out;

    cudaFuncSetAttribute(conv_mma_f16, cudaFuncAttributeMaxDynamicSharedMemorySize, SMEM_BYTES);
    dim3 grid(32, 32);   // (row-quad, batch)
    conv_mma_f16<<<grid, 256, SMEM_BYTES>>>(x, params, out);
}

// round 15
// speedup vs baseline: 1.2216x; 1.2032x over previous
#include <cuda_runtime.h>
#include <cuda_fp16.h>
#include <cstdint>

#define WSIZE 9216
#define PSTRIDE 9248

#define XPITCH 20                        // words/pixel: 16 data + 4 pad (conflict-free, proven R5)
#define XROWW  (130 * XPITCH)            // 2600
#define XT_WORDS (6 * XROWW)             // 15600
#define WPITCH 148                       // words/filter: 144 data + 4 pad (proven R5)
#define WT_WORDS (32 * WPITCH)           // 4736
#define SMEM_BYTES ((XT_WORDS + WT_WORDS) * 4)   // 81344 -> 2 CTAs/SM

// precomputed W^T fp16, plain k-major: [b][f][WPITCH words], word w = (k=2w,2w+1)
__device__ uint32_t gWT[32 * WT_WORDS];

__device__ __forceinline__ uint32_t pack2(float a, float b) {
    __half2 h = __floats2half2_rn(a, b);
    return *(uint32_t*)&h;
}
__device__ __forceinline__ void mma_f16(float& c0, float& c1, float& c2, float& c3,
                                        uint32_t a0, uint32_t a1, uint32_t a2, uint32_t a3,
                                        uint32_t b0, uint32_t b1) {
    asm volatile(
        "mma.sync.aligned.m16n8k16.row.col.f32.f16.f16.f32 "
        "{%0,%1,%2,%3}, {%4,%5,%6,%7}, {%8,%9}, {%0,%1,%2,%3};"
        : "+f"(c0), "+f"(c1), "+f"(c2), "+f"(c3)
        : "r"(a0), "r"(a1), "r"(a2), "r"(a3), "r"(b0), "r"(b1));
}

// ---- precompute W^T fp16 (plain k-major), 9 small blocks per batch ----
__global__ __launch_bounds__(256)
void wprep(const float* __restrict__ params) {
    __shared__ float s[32 * 33];
    const int b  = blockIdx.x / 9;
    const int kc = blockIdx.x % 9;       // k chunk [kc*32, kc*32+32)
    const int tid = threadIdx.x;
    const float* pw = params + (long)b * PSTRIDE + kc * 1024;
    #pragma unroll
    for (int i = tid; i < 1024; i += 256) {
        int k = i >> 5, f = i & 31;
        s[k * 33 + f] = pw[i];
    }
    __syncthreads();
    uint32_t* gw = gWT + b * WT_WORDS + kc * 16;
    #pragma unroll
    for (int i = tid; i < 512; i += 256) {
        int f = i >> 4, n = i & 15;
        gw[f * WPITCH + n] = pack2(s[(2 * n) * 33 + f], s[(2 * n + 1) * 33 + f]);
    }
}

__global__ __launch_bounds__(256, 2)
void conv_mma_f16(const float* __restrict__ x, const float* __restrict__ params,
                  float* __restrict__ out) {
    extern __shared__ uint32_t smem[];
    uint32_t* sX = smem;                 // [row 0..5][pix 0..129][XPITCH], fp16 k-major
    uint32_t* sW = smem + XT_WORDS;      // [f][WPITCH], fp16 k-major

    const int tid = threadIdx.x;
    const int wid = tid >> 5;
    const int lid = tid & 31;
    const int g   = lid >> 2;
    const int t   = lid & 3;
    const int y0  = blockIdx.x * 4;      // 4 output rows per CTA
    const int b   = blockIdx.y;

    // ---- build X tile first (independent of wprep results) ----
    const float* xb = x + (long)b * (128 * 128 * 32);
    #pragma unroll
    for (int it = 0; it < 24; it++) {
        int idx = tid + it * 256;        // 0..6143
        int c4  = idx & 7;
        int px  = (idx >> 3) & 127;
        int row = idx >> 10;             // 0..5
        int gy  = y0 + row - 1;
        uint2 v = make_uint2(0u, 0u);
        if ((unsigned)gy < 128u) {
            float4 s = *(const float4*)(xb + ((gy * 128 + px) * 32 + c4 * 4));
            v.x = pack2(s.x, s.y);
            v.y = pack2(s.z, s.w);
        }
        *(uint2*)(sX + row * XROWW + (px + 1) * XPITCH + c4 * 2) = v;
    }
    if (tid < 192) {
        int row = tid >> 5, rem = tid & 31;
        int pix = (rem >> 4) ? 129 : 0;
        sX[row * XROWW + pix * XPITCH + (rem & 15)] = 0u;
    }

    // ---- PDL: wait for wprep completion, then copy W^T (uint4 memcpy) ----
    asm volatile("griddepcontrol.wait;" ::: "memory");
    const uint4* gw4 = (const uint4*)(gWT + b * WT_WORDS);
    #pragma unroll
    for (int it = 0; it < 5; it++) {
        int idx = tid + it * 256;
        if (idx < WT_WORDS / 4) ((uint4*)sW)[idx] = gw4[idx];
    }
    __syncthreads();

    const int yl = wid >> 1;             // local output row 0..3
    const int m0 = (wid & 1) * 64;       // 64 px per warp

    float acc[4][4][4];
    #pragma unroll
    for (int mi = 0; mi < 4; mi++)
        #pragma unroll
        for (int nt = 0; nt < 4; nt++)
            #pragma unroll
            for (int j = 0; j < 4; j++) acc[mi][nt][j] = 0.f;

    #pragma unroll
    for (int kh = 0; kh < 3; kh++) {
        const uint32_t* xr = sX + (yl + kh) * XROWW;
        #pragma unroll
        for (int kw = 0; kw < 3; kw++) {
            #pragma unroll
            for (int c16 = 0; c16 < 2; c16++) {
                const int k0w = kh * 48 + kw * 16 + c16 * 8;

                // B fragments (scalar LDS, proven conflict-free)
                uint32_t b0[4], b1[4];
                const uint32_t* wp = sW + k0w + t;
                #pragma unroll
                for (int nt = 0; nt < 4; nt++) {
                    int f = nt * 8 + g;
                    b0[nt] = wp[f * WPITCH];
                    b1[nt] = wp[f * WPITCH + 4];
                }

                #pragma unroll
                for (int mi = 0; mi < 4; mi++) {
                    const uint32_t* ap = xr + (m0 + mi * 16 + g + kw) * XPITCH
                                            + c16 * 8 + t;
                    uint32_t a0 = ap[0];
                    uint32_t a1 = ap[8 * XPITCH];
                    uint32_t a2 = ap[4];
                    uint32_t a3 = ap[8 * XPITCH + 4];
                    #pragma unroll
                    for (int nt = 0; nt < 4; nt++)
                        mma_f16(acc[mi][nt][0], acc[mi][nt][1],
                                acc[mi][nt][2], acc[mi][nt][3],
                                a0, a1, a2, a3, b0[nt], b1[nt]);
                }
            }
        }
    }

    // ---- epilogue: + bias, direct STG (R5-proven) ----
    const float* bp = params + (long)b * PSTRIDE + WSIZE;
    float* ob = out + ((long)(b * 128 + y0 + yl)) * 128 * 32;
    #pragma unroll
    for (int nt = 0; nt < 4; nt++) {
        int f = nt * 8 + t * 2;
        float2 bias = *(const float2*)(bp + f);
        #pragma unroll
        for (int mi = 0; mi < 4; mi++) {
            int px = m0 + mi * 16 + g;
            float2 o0, o1;
            o0.x = acc[mi][nt][0] + bias.x;
            o0.y = acc[mi][nt][1] + bias.y;
            o1.x = acc[mi][nt][2] + bias.x;
            o1.y = acc[mi][nt][3] + bias.y;
            *(float2*)(ob + px * 32 + f)       = o0;
            *(float2*)(ob + (px + 8) * 32 + f) = o1;
        }
    }
}

extern "C" void kernel_launch(void* const* d_in, const int* in_sizes, int n_in,
                              void* d_out, int out_size) {
    const float* x      = (const float*)d_in[0];
    const float* params = (const float*)d_in[1];
    float* out          = (float*)d_out;

    wprep<<<288, 256>>>(params);

    cudaFuncSetAttribute(conv_mma_f16, cudaFuncAttributeMaxDynamicSharedMemorySize, SMEM_BYTES);

    // PDL launch: conv may start while wprep finishes; griddepcontrol.wait gates gWT reads
    cudaLaunchConfig_t cfg = {};
    cfg.gridDim  = dim3(32, 32, 1);
    cfg.blockDim = dim3(256, 1, 1);
    cfg.dynamicSmemBytes = SMEM_BYTES;
    cudaLaunchAttribute attrs[1];
    attrs[0].id = cudaLaunchAttributeProgrammaticStreamSerialization;
    attrs[0].val.programmaticStreamSerializationAllowed = 1;
    cfg.attrs = attrs;
    cfg.numAttrs = 1;
    cudaLaunchKernelEx(&cfg, conv_mma_f16, x, params, out);
}

// round 16
// speedup vs baseline: 1.2737x; 1.0427x over previous
#include <cuda_runtime.h>
#include <cuda_fp16.h>
#include <cstdint>

#define WSIZE 9216
#define PSTRIDE 9248

#define XPITCH 20                        // words/pixel: 16 data + 4 pad (conflict-free, proven R5)
#define XROWW  (130 * XPITCH)            // 2600
#define XT_WORDS (6 * XROWW)             // 15600
#define WPITCH 148                       // words/filter: 144 data + 4 pad (proven R5)
#define WT_WORDS (32 * WPITCH)           // 4736
#define SMEM_BYTES ((XT_WORDS + WT_WORDS) * 4)   // 81344 -> 2 CTAs/SM

// precomputed W^T fp16, plain k-major: [b][f][WPITCH words], word w = (k=2w,2w+1)
__device__ uint32_t gWT[32 * WT_WORDS];

__device__ __forceinline__ uint32_t pack2(float a, float b) {
    __half2 h = __floats2half2_rn(a, b);
    return *(uint32_t*)&h;
}
__device__ __forceinline__ void mma_f16(float& c0, float& c1, float& c2, float& c3,
                                        uint32_t a0, uint32_t a1, uint32_t a2, uint32_t a3,
                                        uint32_t b0, uint32_t b1) {
    asm volatile(
        "mma.sync.aligned.m16n8k16.row.col.f32.f16.f16.f32 "
        "{%0,%1,%2,%3}, {%4,%5,%6,%7}, {%8,%9}, {%0,%1,%2,%3};"
        : "+f"(c0), "+f"(c1), "+f"(c2), "+f"(c3)
        : "r"(a0), "r"(a1), "r"(a2), "r"(a3), "r"(b0), "r"(b1));
}

// ---- precompute W^T fp16 (plain k-major), 9 small blocks per batch ----
__global__ __launch_bounds__(256)
void wprep(const float* __restrict__ params) {
    __shared__ float s[32 * 33];
    const int b  = blockIdx.x / 9;
    const int kc = blockIdx.x % 9;       // k chunk [kc*32, kc*32+32)
    const int tid = threadIdx.x;
    const float* pw = params + (long)b * PSTRIDE + kc * 1024;
    #pragma unroll
    for (int i = tid; i < 1024; i += 256) {
        int k = i >> 5, f = i & 31;
        s[k * 33 + f] = pw[i];
    }
    __syncthreads();
    uint32_t* gw = gWT + b * WT_WORDS + kc * 16;
    #pragma unroll
    for (int i = tid; i < 512; i += 256) {
        int f = i >> 4, n = i & 15;
        gw[f * WPITCH + n] = pack2(s[(2 * n) * 33 + f], s[(2 * n + 1) * 33 + f]);
    }
}

__global__ __launch_bounds__(256, 2)
void conv_mma_f16(const float* __restrict__ x, const float* __restrict__ params,
                  float* __restrict__ out) {
    // PDL: gate on wprep completion; everything after is byte-for-byte R5
    asm volatile("griddepcontrol.wait;" ::: "memory");

    extern __shared__ uint32_t smem[];
    uint32_t* sX = smem;                 // [row 0..5][pix 0..129][XPITCH], fp16 k-major
    uint32_t* sW = smem + XT_WORDS;      // [f][WPITCH], fp16 k-major

    const int tid = threadIdx.x;
    const int wid = tid >> 5;
    const int lid = tid & 31;
    const int g   = lid >> 2;
    const int t   = lid & 3;
    const int y0  = blockIdx.x * 4;      // 4 output rows per CTA
    const int b   = blockIdx.y;

    // ---- copy precomputed W^T (uint4 memcpy) ----
    const uint4* gw4 = (const uint4*)(gWT + b * WT_WORDS);
    #pragma unroll
    for (int it = 0; it < 5; it++) {
        int idx = tid + it * 256;
        if (idx < WT_WORDS / 4) ((uint4*)sW)[idx] = gw4[idx];
    }

    // ---- build X tile: input rows y0-1 .. y0+4, pixels -1..128 at 0..129 ----
    const float* xb = x + (long)b * (128 * 128 * 32);
    #pragma unroll
    for (int it = 0; it < 24; it++) {
        int idx = tid + it * 256;        // 0..6143
        int c4  = idx & 7;
        int px  = (idx >> 3) & 127;
        int row = idx >> 10;             // 0..5
        int gy  = y0 + row - 1;
        uint2 v = make_uint2(0u, 0u);
        if ((unsigned)gy < 128u) {
            float4 s = *(const float4*)(xb + ((gy * 128 + px) * 32 + c4 * 4));
            v.x = pack2(s.x, s.y);
            v.y = pack2(s.z, s.w);
        }
        *(uint2*)(sX + row * XROWW + (px + 1) * XPITCH + c4 * 2) = v;
    }
    if (tid < 192) {
        int row = tid >> 5, rem = tid & 31;
        int pix = (rem >> 4) ? 129 : 0;
        sX[row * XROWW + pix * XPITCH + (rem & 15)] = 0u;
    }
    __syncthreads();

    const int yl = wid >> 1;             // local output row 0..3
    const int m0 = (wid & 1) * 64;       // 64 px per warp

    float acc[4][4][4];
    #pragma unroll
    for (int mi = 0; mi < 4; mi++)
        #pragma unroll
        for (int nt = 0; nt < 4; nt++)
            #pragma unroll
            for (int j = 0; j < 4; j++) acc[mi][nt][j] = 0.f;

    #pragma unroll
    for (int kh = 0; kh < 3; kh++) {
        const uint32_t* xr = sX + (yl + kh) * XROWW;
        #pragma unroll
        for (int kw = 0; kw < 3; kw++) {
            #pragma unroll
            for (int c16 = 0; c16 < 2; c16++) {
                const int k0w = kh * 48 + kw * 16 + c16 * 8;

                // B fragments (scalar LDS, proven conflict-free)
                uint32_t b0[4], b1[4];
                const uint32_t* wp = sW + k0w + t;
                #pragma unroll
                for (int nt = 0; nt < 4; nt++) {
                    int f = nt * 8 + g;
                    b0[nt] = wp[f * WPITCH];
                    b1[nt] = wp[f * WPITCH + 4];
                }

                #pragma unroll
                for (int mi = 0; mi < 4; mi++) {
                    const uint32_t* ap = xr + (m0 + mi * 16 + g + kw) * XPITCH
                                            + c16 * 8 + t;
                    uint32_t a0 = ap[0];
                    uint32_t a1 = ap[8 * XPITCH];
                    uint32_t a2 = ap[4];
                    uint32_t a3 = ap[8 * XPITCH + 4];
                    #pragma unroll
                    for (int nt = 0; nt < 4; nt++)
                        mma_f16(acc[mi][nt][0], acc[mi][nt][1],
                                acc[mi][nt][2], acc[mi][nt][3],
                                a0, a1, a2, a3, b0[nt], b1[nt]);
                }
            }
        }
    }

    // ---- epilogue: + bias, direct STG (R5-proven) ----
    const float* bp = params + (long)b * PSTRIDE + WSIZE;
    float* ob = out + ((long)(b * 128 + y0 + yl)) * 128 * 32;
    #pragma unroll
    for (int nt = 0; nt < 4; nt++) {
        int f = nt * 8 + t * 2;
        float2 bias = *(const float2*)(bp + f);
        #pragma unroll
        for (int mi = 0; mi < 4; mi++) {
            int px = m0 + mi * 16 + g;
            float2 o0, o1;
            o0.x = acc[mi][nt][0] + bias.x;
            o0.y = acc[mi][nt][1] + bias.y;
            o1.x = acc[mi][nt][2] + bias.x;
            o1.y = acc[mi][nt][3] + bias.y;
            *(float2*)(ob + px * 32 + f)       = o0;
            *(float2*)(ob + (px + 8) * 32 + f) = o1;
        }
    }
}

extern "C" void kernel_launch(void* const* d_in, const int* in_sizes, int n_in,
                              void* d_out, int out_size) {
    const float* x      = (const float*)d_in[0];
    const float* params = (const float*)d_in[1];
    float* out          = (float*)d_out;

    wprep<<<288, 256>>>(params);

    cudaFuncSetAttribute(conv_mma_f16, cudaFuncAttributeMaxDynamicSharedMemorySize, SMEM_BYTES);

    // PDL launch: conv prologue overlaps wprep tail; entry wait gates gWT reads
    cudaLaunchConfig_t cfg = {};
    cfg.gridDim  = dim3(32, 32, 1);
    cfg.blockDim = dim3(256, 1, 1);
    cfg.dynamicSmemBytes = SMEM_BYTES;
    cudaLaunchAttribute attrs[1];
    attrs[0].id = cudaLaunchAttributeProgrammaticStreamSerialization;
    attrs[0].val.programmaticStreamSerializationAllowed = 1;
    cfg.attrs = attrs;
    cfg.numAttrs = 1;
    cudaLaunchKernelEx(&cfg, conv_mma_f16, x, params, out);
}